// round 1
// baseline (speedup 1.0000x reference)
#include <cuda_runtime.h>

// Problem shape (fixed by the dataset): N=8, T=256, U=128, C=512.
#define N_DIM  8
#define T_DIM  256
#define U_DIM  128
#define U1_DIM 129
#define C_DIM  512
#define ROWS   (N_DIM * T_DIM * U1_DIM)   // 264192

// Scratch (no cudaMalloc allowed): blank/emit log-probs + per-sample losses.
static __device__ float g_blank[ROWS];
static __device__ float g_emit[ROWS];
static __device__ float g_loss[N_DIM];

// ---------------------------------------------------------------------------
// Kernel 1: per-row logsumexp over C=512, then write
//   blank[r] = act[r,0]      - lse
//   emit [r] = act[r,tgt[u]] - lse   (only for u < U)
// One warp per row; 4x float4 per lane = 16 floats/lane = 512/row. Fully
// coalesced streaming read of 541 MB -> HBM-bound.
// ---------------------------------------------------------------------------
__global__ void __launch_bounds__(256) lse_kernel(const float* __restrict__ act,
                                                  const int*   __restrict__ tgt) {
    int gw   = (blockIdx.x * 256 + threadIdx.x) >> 5;   // global warp = row id
    int lane = threadIdx.x & 31;
    if (gw >= ROWS) return;

    const float4* p4 = reinterpret_cast<const float4*>(act) + (size_t)gw * (C_DIM / 4);
    float4 a = p4[lane];
    float4 b = p4[lane + 32];
    float4 c = p4[lane + 64];
    float4 d = p4[lane + 96];

    float m = fmaxf(fmaxf(fmaxf(a.x, a.y), fmaxf(a.z, a.w)),
                    fmaxf(fmaxf(b.x, b.y), fmaxf(b.z, b.w)));
    m = fmaxf(m, fmaxf(fmaxf(fmaxf(c.x, c.y), fmaxf(c.z, c.w)),
                       fmaxf(fmaxf(d.x, d.y), fmaxf(d.z, d.w))));
#pragma unroll
    for (int o = 16; o; o >>= 1)
        m = fmaxf(m, __shfl_xor_sync(0xffffffffu, m, o));

    float s = __expf(a.x - m) + __expf(a.y - m) + __expf(a.z - m) + __expf(a.w - m);
    s += __expf(b.x - m) + __expf(b.y - m) + __expf(b.z - m) + __expf(b.w - m);
    s += __expf(c.x - m) + __expf(c.y - m) + __expf(c.z - m) + __expf(c.w - m);
    s += __expf(d.x - m) + __expf(d.y - m) + __expf(d.z - m) + __expf(d.w - m);
#pragma unroll
    for (int o = 16; o; o >>= 1)
        s += __shfl_xor_sync(0xffffffffu, s, o);

    if (lane == 0) {
        float lse = m + __logf(s);
        g_blank[gw] = a.x - lse;              // lane 0's a.x == act[row, 0] (BLANK)
        int u = gw % U1_DIM;
        if (u < U_DIM) {
            int n  = gw / (T_DIM * U1_DIM);
            int tv = __ldg(tgt + n * U_DIM + u);
            const float* p = act + (size_t)gw * C_DIM;
            g_emit[gw] = __ldg(p + tv) - lse; // L1-hot: same warp just read this row
        }
    }
}

// ---------------------------------------------------------------------------
// Kernel 2: alpha forward recursion via anti-diagonal wavefront.
//   alpha[t][u] = logaddexp(alpha[t-1][u] + blank[t-1][u],
//                           alpha[t][u-1] + emit [t][u-1])
//   alpha[0][0] = 0; t==0 / u==0 edges take the single available path.
// One CTA per batch item. Diagonal d depends only on d-1 -> double-buffered
// shared row + one __syncthreads per diagonal. Global bl/em operands are
// prefetched 8 diagonals ahead into registers (addresses are pure f(d,u)),
// so the L2 latency (~250cyc) is paid once per 8 diagonals, not per diagonal.
// ---------------------------------------------------------------------------
__global__ void __launch_bounds__(160) alpha_kernel(const int* __restrict__ tlen,
                                                    const int* __restrict__ ulen) {
    int n = blockIdx.x;
    const float* bl = g_blank + (size_t)n * T_DIM * U1_DIM;
    const float* em = g_emit  + (size_t)n * T_DIM * U1_DIM;

    __shared__ float buf[2][U1_DIM + 3];

    int u  = threadIdx.x;             // 0..159; 0..128 active
    int Tn = __ldg(tlen + n);
    int Un = __ldg(ulen + n);

    if (u == 0) buf[0][0] = 0.0f;     // alpha[0][0]
    __syncthreads();

    int cur = 1;
    const int DMAX = T_DIM + U_DIM - 1;   // 383

    for (int d0 = 1; d0 <= DMAX; d0 += 8) {
        float blv[8], emv[8];
        if (u <= U_DIM) {
#pragma unroll
            for (int k = 0; k < 8; ++k) {
                int t  = d0 + k - u;
                int tb = min(max(t - 1, 0), T_DIM - 1);   // clamp: unused when invalid
                int te = min(max(t,     0), T_DIM - 1);
                blv[k] = __ldg(bl + tb * U1_DIM + u);
                emv[k] = __ldg(em + te * U1_DIM + max(u - 1, 0));
            }
        }
#pragma unroll
        for (int k = 0; k < 8; ++k) {
            int d = d0 + k;
            if (d <= DMAX) {
                int lo = max(0, d - (T_DIM - 1));
                if (u >= lo && u <= min(U_DIM, d)) {
                    int t = d - u;
                    float val;
                    if (t == 0) {
                        val = buf[cur ^ 1][u - 1] + emv[k];
                    } else if (u == 0) {
                        val = buf[cur ^ 1][0] + blv[k];
                    } else {
                        float pa = buf[cur ^ 1][u]     + blv[k];
                        float pb = buf[cur ^ 1][u - 1] + emv[k];
                        float mx = fmaxf(pa, pb);
                        val = mx + log1pf(__expf(fminf(pa, pb) - mx));
                    }
                    buf[cur][u] = val;
                    if (t == Tn - 1 && u == Un) {
                        g_loss[n] = -(val + __ldg(bl + (Tn - 1) * U1_DIM + Un));
                    }
                }
            }
            __syncthreads();
            cur ^= 1;
        }
    }
}

// ---------------------------------------------------------------------------
// Kernel 3: mean over N losses -> scalar output.
// ---------------------------------------------------------------------------
__global__ void mean_kernel(float* __restrict__ out) {
    if (threadIdx.x == 0) {
        float s = 0.0f;
#pragma unroll
        for (int i = 0; i < N_DIM; ++i) s += g_loss[i];
        out[0] = s / (float)N_DIM;
    }
}

extern "C" void kernel_launch(void* const* d_in, const int* in_sizes, int n_in,
                              void* d_out, int out_size) {
    const float* act  = (const float*)d_in[0];
    const int*   tgt  = (const int*)  d_in[1];
    const int*   tlen = (const int*)  d_in[2];
    const int*   ulen = (const int*)  d_in[3];
    float*       out  = (float*)      d_out;

    // one warp per row, 8 warps per block
    int blocks = (ROWS + 7) / 8;
    lse_kernel<<<blocks, 256>>>(act, tgt);
    alpha_kernel<<<N_DIM, 160>>>(tlen, ulen);
    mean_kernel<<<1, 32>>>(out);
}

// round 2
// speedup vs baseline: 1.2491x; 1.2491x over previous
#include <cuda_runtime.h>

// Problem shape (fixed by the dataset): N=8, T=256, U=128, C=512.
#define N_DIM  8
#define T_DIM  256
#define U_DIM  128
#define U1_DIM 129
#define C_DIM  512
#define ROWS   (N_DIM * T_DIM * U1_DIM)   // 264192

// Diagonal-major scratch: index [d = t+u][pos = u], pitch 132.
#define PITCH   132
#define DIAGS   (T_DIM + U_DIM)           // 384
#define DIAG_SZ (DIAGS * PITCH)           // 50688 per sample

#define CH      4                          // rounds per prefetch chunk
#define NROUND  ((T_DIM + U_DIM) / 2)      // 192 rounds, 2 diagonals each
#define NCH     (NROUND / CH)              // 48

static __device__ float g_bld[N_DIM * DIAG_SZ + 512];   // blank, diag-major
static __device__ float g_emd[N_DIM * DIAG_SZ + 512];   // emit,  diag-major
static __device__ float g_loss[N_DIM];

__device__ __forceinline__ float laddexp(float a, float b) {
    float mx = fmaxf(a, b);
    return mx + __logf(1.0f + __expf(fminf(a, b) - mx));
}

// ---------------------------------------------------------------------------
// Kernel 1: per-row logsumexp over C=512; write blank/emit log-probs into
// DIAGONAL-major scratch so the wavefront kernel reads coalesced rows.
// One warp per row, 4x float4 per lane. HBM-bound streaming (541 MB).
// ---------------------------------------------------------------------------
__global__ void __launch_bounds__(256) lse_kernel(const float* __restrict__ act,
                                                  const int*   __restrict__ tgt) {
    int gw   = (blockIdx.x * 256 + threadIdx.x) >> 5;   // global warp = row id
    int lane = threadIdx.x & 31;
    if (gw >= ROWS) return;

    const float4* p4 = reinterpret_cast<const float4*>(act) + (size_t)gw * (C_DIM / 4);
    float4 a = p4[lane];
    float4 b = p4[lane + 32];
    float4 c = p4[lane + 64];
    float4 d = p4[lane + 96];

    float m = fmaxf(fmaxf(fmaxf(a.x, a.y), fmaxf(a.z, a.w)),
                    fmaxf(fmaxf(b.x, b.y), fmaxf(b.z, b.w)));
    m = fmaxf(m, fmaxf(fmaxf(fmaxf(c.x, c.y), fmaxf(c.z, c.w)),
                       fmaxf(fmaxf(d.x, d.y), fmaxf(d.z, d.w))));
#pragma unroll
    for (int o = 16; o; o >>= 1)
        m = fmaxf(m, __shfl_xor_sync(0xffffffffu, m, o));

    float s = __expf(a.x - m) + __expf(a.y - m) + __expf(a.z - m) + __expf(a.w - m);
    s += __expf(b.x - m) + __expf(b.y - m) + __expf(b.z - m) + __expf(b.w - m);
    s += __expf(c.x - m) + __expf(c.y - m) + __expf(c.z - m) + __expf(c.w - m);
    s += __expf(d.x - m) + __expf(d.y - m) + __expf(d.z - m) + __expf(d.w - m);
#pragma unroll
    for (int o = 16; o; o >>= 1)
        s += __shfl_xor_sync(0xffffffffu, s, o);

    if (lane == 0) {
        float lse = m + __logf(s);
        int n   = gw / (T_DIM * U1_DIM);
        int rem = gw % (T_DIM * U1_DIM);
        int t   = rem / U1_DIM;
        int u   = rem % U1_DIM;
        size_t db = (size_t)n * DIAG_SZ + (size_t)(t + u) * PITCH + u;
        g_bld[db] = a.x - lse;                 // lane 0's a.x == act[row, BLANK=0]
        if (u < U_DIM) {
            int tv = __ldg(tgt + n * U_DIM + u);
            g_emd[db] = __ldg(act + (size_t)gw * C_DIM + tv) - lse;  // L1-hot
        }
    }
}

// ---------------------------------------------------------------------------
// Kernel 2: alpha forward recursion, anti-diagonal wavefront, 2 diags/round.
//   cell (t,u), d=t+u:  alpha = laddexp(alpha[t-1][u] + bl[t-1][u],
//                                       alpha[t][u-1] + em[t][u-1])
//   Both operands live on stored diagonal d-1: bl at pos u, em at pos u-1
//   -> coalesced loads. Diag d0 from shared prev row; diag d0+1 takes its
//   u-1 neighbor via shfl_up (warp-boundary lanes recompute it redundantly,
//   off the critical path). One __syncthreads per round (2 diagonals).
//   Global operands double-buffer-prefetched CH rounds ahead in registers.
// ---------------------------------------------------------------------------
struct Ops {
    float bl0[CH], em0[CH], bl1[CH], em1[CH], bl0m[CH], em0m[CH];
};

__device__ __forceinline__ void load_chunk(Ops& o, int r0,
                                           const float* __restrict__ bld,
                                           const float* __restrict__ emd, int u) {
    int um1 = max(u - 1, 0), um2 = max(u - 2, 0);
#pragma unroll
    for (int k = 0; k < CH; ++k) {
        int d0 = 2 * (r0 + k) - 1;
        const float* b0 = bld + (d0 - 1) * PITCH;
        const float* e0 = emd + (d0 - 1) * PITCH;
        o.bl0[k]  = __ldg(b0 + u);
        o.em0[k]  = __ldg(e0 + um1);
        o.bl0m[k] = __ldg(b0 + um1);           // only used by warp-boundary lanes
        o.em0m[k] = __ldg(e0 + um2);
        o.bl1[k]  = __ldg(b0 + PITCH + u);     // diag d0 row (operands for d0+1)
        o.em1[k]  = __ldg(e0 + PITCH + um1);
    }
}

__global__ void __launch_bounds__(160, 1) alpha_kernel(const int* __restrict__ tlen,
                                                       const int* __restrict__ ulen) {
    int n = blockIdx.x;
    const float* bld = g_bld + (size_t)n * DIAG_SZ;
    const float* emd = g_emd + (size_t)n * DIAG_SZ;

    __shared__ float buf[2][160];

    int u   = threadIdx.x;                    // 0..159 (all lanes run uniformly)
    int Tn  = __ldg(tlen + n);
    int Un  = __ldg(ulen + n);
    int Tm1 = Tn - 1;

    if (u == 0) buf[0][0] = 0.0f;             // alpha[0][0]
    __syncthreads();

    int um1 = max(u - 1, 0);
    int um2 = max(u - 2, 0);
    bool bdry = ((u & 31) == 0) && (u > 0);   // lanes needing cross-warp neighbor

    Ops A, B;
    load_chunk(A, 1, bld, emd, u);
    int cur = 1;

    for (int c = 0; c < NCH; ++c) {
        int r0 = 1 + c * CH;
        if (c + 1 < NCH) load_chunk(B, r0 + CH, bld, emd, u);
#pragma unroll
        for (int k = 0; k < CH; ++k) {
            int r  = r0 + k;
            int d0 = 2 * r - 1, d1 = 2 * r;
            const float* prv = buf[cur ^ 1];
            float*       nxt = buf[cur];

            float p_u  = prv[u];
            float p_um = prv[um1];

            // ---- diagonal d0 (cell t0 = d0 - u) ----
            int   t0 = d0 - u;
            float v0;
            if (t0 == 0)      v0 = p_um + A.em0[k];        // top row: emit path only
            else if (u == 0)  v0 = p_u  + A.bl0[k];        // left col: blank path only
            else              v0 = laddexp(p_u + A.bl0[k], p_um + A.em0[k]);
            if (t0 == Tm1 && u == Un)
                g_loss[n] = -(v0 + __ldg(bld + (Tm1 + Un) * PITCH + Un));

            // ---- neighbor a_d0[u-1] for diagonal d1 ----
            float nb = __shfl_up_sync(0xffffffffu, v0, 1);
            if (bdry) {                                    // redundant recompute, independent of v0
                float q_um = prv[um2];
                if (d0 == u - 1) nb = q_um + A.em0m[k];    // neighbor is its top-row cell
                else             nb = laddexp(p_um + A.bl0m[k], q_um + A.em0m[k]);
            }

            // ---- diagonal d1 (cell t1 = d1 - u) ----
            int   t1 = d1 - u;
            float v1;
            if (t1 == 0)      v1 = nb + A.em1[k];
            else if (u == 0)  v1 = v0 + A.bl1[k];
            else              v1 = laddexp(v0 + A.bl1[k], nb + A.em1[k]);

            if (u >= d1 - (T_DIM - 1) && u <= min(U_DIM, d1)) {
                nxt[u] = v1;
                if (t1 == Tm1 && u == Un)
                    g_loss[n] = -(v1 + __ldg(bld + (Tm1 + Un) * PITCH + Un));
            }
            __syncthreads();
            cur ^= 1;
        }
        A = B;
    }
}

// ---------------------------------------------------------------------------
// Kernel 3: mean over N losses -> scalar output (deterministic, no atomics).
// ---------------------------------------------------------------------------
__global__ void mean_kernel(float* __restrict__ out) {
    if (threadIdx.x == 0) {
        float s = 0.0f;
#pragma unroll
        for (int i = 0; i < N_DIM; ++i) s += g_loss[i];
        out[0] = s / (float)N_DIM;
    }
}

extern "C" void kernel_launch(void* const* d_in, const int* in_sizes, int n_in,
                              void* d_out, int out_size) {
    const float* act  = (const float*)d_in[0];
    const int*   tgt  = (const int*)  d_in[1];
    const int*   tlen = (const int*)  d_in[2];
    const int*   ulen = (const int*)  d_in[3];
    float*       out  = (float*)      d_out;

    int blocks = (ROWS + 7) / 8;              // one warp per row, 8 warps/block
    lse_kernel<<<blocks, 256>>>(act, tgt);
    alpha_kernel<<<N_DIM, 160>>>(tlen, ulen);
    mean_kernel<<<1, 32>>>(out);
}

// round 3
// speedup vs baseline: 1.3951x; 1.1169x over previous
#include <cuda_runtime.h>

// Problem shape (fixed by the dataset): N=8, T=256, U=128, C=512.
#define N_DIM  8
#define T_DIM  256
#define U_DIM  128
#define U1_DIM 129
#define C_DIM  512
#define ROWS   (N_DIM * T_DIM * U1_DIM)   // 264192

// Diagonal-major scratch: cell (t,u) lives at [d = t+u][col = u], pitch 132.
#define PITCH   132
#define DIAGS   (T_DIM + U_DIM)           // 384
#define DIAG_SZ (DIAGS * PITCH)           // 50688 per sample

#define NEG     (-1.0e30f)                // finite "-inf": exp underflows to 0,
                                          // no NaN via fmaxf, no overflow in 384 steps
#define CH      4                         // diagonals per prefetch chunk
#define NCHUNK  96                        // 384 diagonals (d = 1..384)

static __device__ __align__(16) float g_bld[N_DIM * DIAG_SZ + 512];  // blank, diag-major
static __device__ __align__(16) float g_emd[N_DIM * DIAG_SZ + 512];  // emit,  diag-major
static __device__ float g_loss[N_DIM];

__device__ __forceinline__ float laddexp(float x, float y) {
    float mx = fmaxf(x, y);
    return mx + __logf(1.0f + __expf(fminf(x, y) - mx));
}

// ---------------------------------------------------------------------------
// Kernel 0: flood scratch with NEG so unwritten (pad) slots act as -inf.
// Top-row / left-col edge cells then need no branches in the wavefront:
// the dead path's addend is NEG -> exp()==0 -> single-path result, exactly.
// ---------------------------------------------------------------------------
__global__ void fill_kernel() {
    const int n4 = (N_DIM * DIAG_SZ + 512) / 4;
    float4 v = make_float4(NEG, NEG, NEG, NEG);
    float4* b = reinterpret_cast<float4*>(g_bld);
    float4* e = reinterpret_cast<float4*>(g_emd);
    for (int i = blockIdx.x * blockDim.x + threadIdx.x; i < n4;
         i += gridDim.x * blockDim.x) {
        b[i] = v;
        e[i] = v;
    }
}

// ---------------------------------------------------------------------------
// Kernel 1: per-row logsumexp over C=512; write blank/emit log-probs into
// diagonal-major scratch. One warp per row, 4x float4 per lane. HBM-bound
// (541 MB stream, measured 84.7% DRAM = at the ceiling).
// ---------------------------------------------------------------------------
__global__ void __launch_bounds__(256) lse_kernel(const float* __restrict__ act,
                                                  const int*   __restrict__ tgt) {
    int gw   = (blockIdx.x * 256 + threadIdx.x) >> 5;   // global warp = row id
    int lane = threadIdx.x & 31;
    if (gw >= ROWS) return;

    const float4* p4 = reinterpret_cast<const float4*>(act) + (size_t)gw * (C_DIM / 4);
    float4 a = p4[lane];
    float4 b = p4[lane + 32];
    float4 c = p4[lane + 64];
    float4 d = p4[lane + 96];

    float m = fmaxf(fmaxf(fmaxf(a.x, a.y), fmaxf(a.z, a.w)),
                    fmaxf(fmaxf(b.x, b.y), fmaxf(b.z, b.w)));
    m = fmaxf(m, fmaxf(fmaxf(fmaxf(c.x, c.y), fmaxf(c.z, c.w)),
                       fmaxf(fmaxf(d.x, d.y), fmaxf(d.z, d.w))));
#pragma unroll
    for (int o = 16; o; o >>= 1)
        m = fmaxf(m, __shfl_xor_sync(0xffffffffu, m, o));

    float s = __expf(a.x - m) + __expf(a.y - m) + __expf(a.z - m) + __expf(a.w - m);
    s += __expf(b.x - m) + __expf(b.y - m) + __expf(b.z - m) + __expf(b.w - m);
    s += __expf(c.x - m) + __expf(c.y - m) + __expf(c.z - m) + __expf(c.w - m);
    s += __expf(d.x - m) + __expf(d.y - m) + __expf(d.z - m) + __expf(d.w - m);
#pragma unroll
    for (int o = 16; o; o >>= 1)
        s += __shfl_xor_sync(0xffffffffu, s, o);

    if (lane == 0) {
        float lse = m + __logf(s);
        int n   = gw / (T_DIM * U1_DIM);
        int rem = gw % (T_DIM * U1_DIM);
        int t   = rem / U1_DIM;
        int u   = rem % U1_DIM;
        size_t db = (size_t)n * DIAG_SZ + (size_t)(t + u) * PITCH + u;
        g_bld[db] = a.x - lse;                 // lane 0's a.x == act[row, BLANK=0]
        if (u < U_DIM) {
            int tv = __ldg(tgt + n * U_DIM + u);
            g_emd[db] = __ldg(act + (size_t)gw * C_DIM + tv) - lse;  // L1-hot
        }
    }
}

// ---------------------------------------------------------------------------
// Kernel 2: alpha wavefront, ONE WARP per sample, fully register-resident.
//   cell (t,u), d=t+u:  alpha = laddexp(alpha[t-1][u] + bl@[d-1][u],
//                                       alpha[t][u-1] + em@[d-1][u-1])
// Lane L owns u = 4L+1..4L+4 (a[0..3]); u=0 is the blank-only FADD chain a0
// (kept warp-uniform via one broadcast shfl). Per diagonal:
//   2x float4 + 1 scalar LDG (coalesced diag row), 1 shfl_up, 4 laddexp.
// No shared memory, no __syncthreads, no divergent branches. Operands are
// double-buffer-prefetched CH=4 diagonals ahead (chunk compute ~280cyc hides
// L2 ~250cyc). Edge cells resolve through the NEG pads.
// ---------------------------------------------------------------------------
struct Chunk {
    float4 bl[CH];   // bl row d-1, cols 4L..4L+3
    float4 em[CH];   // em row d-1, cols 4L..4L+3
    float  blx[CH];  // bl row d-1, col 4L+4
};

__device__ __forceinline__ void ldchunk(Chunk& c, const float* __restrict__ bld,
                                        const float* __restrict__ emd,
                                        int dstart, int L) {
#pragma unroll
    for (int k = 0; k < CH; ++k) {
        const float* rb = bld + (size_t)(dstart + k - 1) * PITCH + 4 * L;
        const float* re = emd + (size_t)(dstart + k - 1) * PITCH + 4 * L;
        c.bl[k]  = __ldg(reinterpret_cast<const float4*>(rb));
        c.em[k]  = __ldg(reinterpret_cast<const float4*>(re));
        c.blx[k] = __ldg(rb + 4);
    }
}

__global__ void __launch_bounds__(32, 1) alpha_kernel(const int* __restrict__ tlen,
                                                      const int* __restrict__ ulen) {
    int n = blockIdx.x;
    int L = threadIdx.x;
    const float* bld = g_bld + (size_t)n * DIAG_SZ;
    const float* emd = g_emd + (size_t)n * DIAG_SZ;

    int Tn = __ldg(tlen + n);
    int Un = __ldg(ulen + n);
    int dLoss = Tn - 1 + Un;

    float a0 = 0.0f;                         // alpha[0][0]
    float a[4] = {NEG, NEG, NEG, NEG};

    if (dLoss == 0 && L == 0)                // degenerate Tn=1, Un=0
        g_loss[n] = -(a0 + __ldg(bld));

    Chunk A, B;
    ldchunk(A, bld, emd, 1, L);

    int d = 1;
    for (int c = 0; c < NCHUNK; ++c) {
        if (c + 1 < NCHUNK) ldchunk(B, bld, emd, d + CH, L);
#pragma unroll
        for (int k = 0; k < CH; ++k, ++d) {
            float4 bl4 = A.bl[k];
            float4 em4 = A.em[k];
            float  blx = A.blx[k];

            float nb_in = __shfl_up_sync(0xffffffffu, a[3], 1);   // lane L-1's a3 = aprev[4L]
            float nb    = (L == 0) ? a0 : nb_in;
            float bl00  = __shfl_sync(0xffffffffu, bl4.x, 0);     // bl[d-1][0] broadcast

            // cells u = 4L+1 .. 4L+4  (bl at col u -> bl4.yzw/blx; em at col u-1 -> em4.xyzw)
            float t0 = laddexp(a[0] + bl4.y, nb   + em4.x);
            float t1 = laddexp(a[1] + bl4.z, a[0] + em4.y);
            float t2 = laddexp(a[2] + bl4.w, a[1] + em4.z);
            float t3 = laddexp(a[3] + blx,   a[2] + em4.w);
            a0 += bl00;                                            // u=0 blank-only chain
            a[0] = t0; a[1] = t1; a[2] = t2; a[3] = t3;

            if (d == dLoss) {                  // warp-uniform, true exactly once
                if (Un == 0) {
                    if (L == 0)
                        g_loss[n] = -(a0 + __ldg(bld + (size_t)dLoss * PITCH));
                } else {
                    int tl = (Un - 1) >> 2, j = (Un - 1) & 3;
                    if (L == tl) {
                        float v = (j == 0) ? t0 : (j == 1) ? t1 : (j == 2) ? t2 : t3;
                        g_loss[n] = -(v + __ldg(bld + (size_t)dLoss * PITCH + Un));
                    }
                }
            }
        }
        A = B;
    }
}

// ---------------------------------------------------------------------------
// Kernel 3: mean over N losses -> scalar output (deterministic).
// ---------------------------------------------------------------------------
__global__ void mean_kernel(float* __restrict__ out) {
    if (threadIdx.x == 0) {
        float s = 0.0f;
#pragma unroll
        for (int i = 0; i < N_DIM; ++i) s += g_loss[i];
        out[0] = s / (float)N_DIM;
    }
}

extern "C" void kernel_launch(void* const* d_in, const int* in_sizes, int n_in,
                              void* d_out, int out_size) {
    const float* act  = (const float*)d_in[0];
    const int*   tgt  = (const int*)  d_in[1];
    const int*   tlen = (const int*)  d_in[2];
    const int*   ulen = (const int*)  d_in[3];
    float*       out  = (float*)      d_out;

    fill_kernel<<<400, 256>>>();
    int blocks = (ROWS + 7) / 8;              // one warp per row, 8 warps/block
    lse_kernel<<<blocks, 256>>>(act, tgt);
    alpha_kernel<<<N_DIM, 32>>>(tlen, ulen);
    mean_kernel<<<1, 32>>>(out);
}

// round 4
// speedup vs baseline: 1.3987x; 1.0026x over previous
#include <cuda_runtime.h>

// Problem shape (fixed by the dataset): N=8, T=256, U=128, C=512.
#define N_DIM  8
#define T_DIM  256
#define U_DIM  128
#define U1_DIM 129
#define C_DIM  512
#define ROWS   (N_DIM * T_DIM * U1_DIM)   // 264192

// Diagonal-major scratch: cell (t,u) lives at [d = t+u][col = u], pitch 132.
#define PITCH   132
#define DIAGS   (T_DIM + U_DIM)           // 384
#define DIAG_SZ (DIAGS * PITCH)           // 50688 per sample

#define NEG     (-1.0e30f)                // finite "-inf": exp underflows to 0,
                                          // no NaN via fmaxf, no overflow in 384 steps
#define CH      4                         // diagonals per prefetch chunk
#define NCHUNK  96                        // 384 diagonals (d = 1..384)

static __device__ __align__(16) float g_bld[N_DIM * DIAG_SZ + 512];  // blank, diag-major
static __device__ __align__(16) float g_emd[N_DIM * DIAG_SZ + 512];  // emit,  diag-major
static __device__ float g_loss[N_DIM];

__device__ __forceinline__ float laddexp(float x, float y) {
    float mx = fmaxf(x, y);
    return mx + __logf(1.0f + __expf(fminf(x, y) - mx));
}

// ---------------------------------------------------------------------------
// Kernel 0: flood scratch with NEG so unwritten (pad) slots act as -inf.
// Top-row / left-col edge cells then need no branches in the wavefront:
// the dead path's addend is NEG -> exp()==0 -> single-path result, exactly.
// ---------------------------------------------------------------------------
__global__ void fill_kernel() {
    const int n4 = (N_DIM * DIAG_SZ + 512) / 4;
    float4 v = make_float4(NEG, NEG, NEG, NEG);
    float4* b = reinterpret_cast<float4*>(g_bld);
    float4* e = reinterpret_cast<float4*>(g_emd);
    for (int i = blockIdx.x * blockDim.x + threadIdx.x; i < n4;
         i += gridDim.x * blockDim.x) {
        b[i] = v;
        e[i] = v;
    }
}

// ---------------------------------------------------------------------------
// Kernel 1: per-row logsumexp over C=512; write blank/emit log-probs into
// diagonal-major scratch. One warp per row, 4x float4 per lane. HBM-bound
// (541 MB stream, measured 84.7% DRAM = at the ceiling).
// ---------------------------------------------------------------------------
__global__ void __launch_bounds__(256) lse_kernel(const float* __restrict__ act,
                                                  const int*   __restrict__ tgt) {
    int gw   = (blockIdx.x * 256 + threadIdx.x) >> 5;   // global warp = row id
    int lane = threadIdx.x & 31;
    if (gw >= ROWS) return;

    const float4* p4 = reinterpret_cast<const float4*>(act) + (size_t)gw * (C_DIM / 4);
    float4 a = p4[lane];
    float4 b = p4[lane + 32];
    float4 c = p4[lane + 64];
    float4 d = p4[lane + 96];

    float m = fmaxf(fmaxf(fmaxf(a.x, a.y), fmaxf(a.z, a.w)),
                    fmaxf(fmaxf(b.x, b.y), fmaxf(b.z, b.w)));
    m = fmaxf(m, fmaxf(fmaxf(fmaxf(c.x, c.y), fmaxf(c.z, c.w)),
                       fmaxf(fmaxf(d.x, d.y), fmaxf(d.z, d.w))));
#pragma unroll
    for (int o = 16; o; o >>= 1)
        m = fmaxf(m, __shfl_xor_sync(0xffffffffu, m, o));

    float s = __expf(a.x - m) + __expf(a.y - m) + __expf(a.z - m) + __expf(a.w - m);
    s += __expf(b.x - m) + __expf(b.y - m) + __expf(b.z - m) + __expf(b.w - m);
    s += __expf(c.x - m) + __expf(c.y - m) + __expf(c.z - m) + __expf(c.w - m);
    s += __expf(d.x - m) + __expf(d.y - m) + __expf(d.z - m) + __expf(d.w - m);
#pragma unroll
    for (int o = 16; o; o >>= 1)
        s += __shfl_xor_sync(0xffffffffu, s, o);

    if (lane == 0) {
        float lse = m + __logf(s);
        int n   = gw / (T_DIM * U1_DIM);
        int rem = gw % (T_DIM * U1_DIM);
        int t   = rem / U1_DIM;
        int u   = rem % U1_DIM;
        size_t db = (size_t)n * DIAG_SZ + (size_t)(t + u) * PITCH + u;
        g_bld[db] = a.x - lse;                 // lane 0's a.x == act[row, BLANK=0]
        if (u < U_DIM) {
            int tv = __ldg(tgt + n * U_DIM + u);
            g_emd[db] = __ldg(act + (size_t)gw * C_DIM + tv) - lse;  // L1-hot
        }
    }
}

// ---------------------------------------------------------------------------
// Kernel 2: alpha wavefront, ONE WARP per sample, fully register-resident.
//   cell (t,u), d=t+u:  alpha = laddexp(alpha[t-1][u] + bl@[d-1][u],
//                                       alpha[t][u-1] + em@[d-1][u-1])
// Lane L owns u = 4L+1..4L+4 (a[0..3]); u=0 is the blank-only FADD chain a0
// (kept warp-uniform via one broadcast shfl). Per diagonal:
//   2x float4 + 1 scalar LDG (coalesced diag row), 1 shfl_up, 4 laddexp.
// No shared memory, no __syncthreads, no divergent branches. Operands are
// double-buffer-prefetched CH=4 diagonals ahead (chunk compute ~280cyc hides
// L2 ~250cyc). Edge cells resolve through the NEG pads.
// ---------------------------------------------------------------------------
struct Chunk {
    float4 bl[CH];   // bl row d-1, cols 4L..4L+3
    float4 em[CH];   // em row d-1, cols 4L..4L+3
    float  blx[CH];  // bl row d-1, col 4L+4
};

__device__ __forceinline__ void ldchunk(Chunk& c, const float* __restrict__ bld,
                                        const float* __restrict__ emd,
                                        int dstart, int L) {
#pragma unroll
    for (int k = 0; k < CH; ++k) {
        const float* rb = bld + (size_t)(dstart + k - 1) * PITCH + 4 * L;
        const float* re = emd + (size_t)(dstart + k - 1) * PITCH + 4 * L;
        c.bl[k]  = __ldg(reinterpret_cast<const float4*>(rb));
        c.em[k]  = __ldg(reinterpret_cast<const float4*>(re));
        c.blx[k] = __ldg(rb + 4);
    }
}

__global__ void __launch_bounds__(32, 1) alpha_kernel(const int* __restrict__ tlen,
                                                      const int* __restrict__ ulen) {
    int n = blockIdx.x;
    int L = threadIdx.x;
    const float* bld = g_bld + (size_t)n * DIAG_SZ;
    const float* emd = g_emd + (size_t)n * DIAG_SZ;

    int Tn = __ldg(tlen + n);
    int Un = __ldg(ulen + n);
    int dLoss = Tn - 1 + Un;

    float a0 = 0.0f;                         // alpha[0][0]
    float a[4] = {NEG, NEG, NEG, NEG};

    if (dLoss == 0 && L == 0)                // degenerate Tn=1, Un=0
        g_loss[n] = -(a0 + __ldg(bld));

    Chunk A, B;
    ldchunk(A, bld, emd, 1, L);

    int d = 1;
    for (int c = 0; c < NCHUNK; ++c) {
        if (c + 1 < NCHUNK) ldchunk(B, bld, emd, d + CH, L);
#pragma unroll
        for (int k = 0; k < CH; ++k, ++d) {
            float4 bl4 = A.bl[k];
            float4 em4 = A.em[k];
            float  blx = A.blx[k];

            float nb_in = __shfl_up_sync(0xffffffffu, a[3], 1);   // lane L-1's a3 = aprev[4L]
            float nb    = (L == 0) ? a0 : nb_in;
            float bl00  = __shfl_sync(0xffffffffu, bl4.x, 0);     // bl[d-1][0] broadcast

            // cells u = 4L+1 .. 4L+4  (bl at col u -> bl4.yzw/blx; em at col u-1 -> em4.xyzw)
            float t0 = laddexp(a[0] + bl4.y, nb   + em4.x);
            float t1 = laddexp(a[1] + bl4.z, a[0] + em4.y);
            float t2 = laddexp(a[2] + bl4.w, a[1] + em4.z);
            float t3 = laddexp(a[3] + blx,   a[2] + em4.w);
            a0 += bl00;                                            // u=0 blank-only chain
            a[0] = t0; a[1] = t1; a[2] = t2; a[3] = t3;

            if (d == dLoss) {                  // warp-uniform, true exactly once
                if (Un == 0) {
                    if (L == 0)
                        g_loss[n] = -(a0 + __ldg(bld + (size_t)dLoss * PITCH));
                } else {
                    int tl = (Un - 1) >> 2, j = (Un - 1) & 3;
                    if (L == tl) {
                        float v = (j == 0) ? t0 : (j == 1) ? t1 : (j == 2) ? t2 : t3;
                        g_loss[n] = -(v + __ldg(bld + (size_t)dLoss * PITCH + Un));
                    }
                }
            }
        }
        A = B;
    }
}

// ---------------------------------------------------------------------------
// Kernel 3: mean over N losses -> scalar output (deterministic).
// ---------------------------------------------------------------------------
__global__ void mean_kernel(float* __restrict__ out) {
    if (threadIdx.x == 0) {
        float s = 0.0f;
#pragma unroll
        for (int i = 0; i < N_DIM; ++i) s += g_loss[i];
        out[0] = s / (float)N_DIM;
    }
}

extern "C" void kernel_launch(void* const* d_in, const int* in_sizes, int n_in,
                              void* d_out, int out_size) {
    const float* act  = (const float*)d_in[0];
    const int*   tgt  = (const int*)  d_in[1];
    const int*   tlen = (const int*)  d_in[2];
    const int*   ulen = (const int*)  d_in[3];
    float*       out  = (float*)      d_out;

    fill_kernel<<<400, 256>>>();
    int blocks = (ROWS + 7) / 8;              // one warp per row, 8 warps/block
    lse_kernel<<<blocks, 256>>>(act, tgt);
    alpha_kernel<<<N_DIM, 32>>>(tlen, ulen);
    mean_kernel<<<1, 32>>>(out);
}

// round 6
// speedup vs baseline: 1.5756x; 1.1265x over previous
#include <cuda_runtime.h>
#include <cstdint>

// Problem shape (fixed by the dataset): N=8, T=256, U=128, C=512.
#define N_DIM  8
#define T_DIM  256
#define U_DIM  128
#define U1_DIM 129
#define C_DIM  512
#define ROWS   (N_DIM * T_DIM * U1_DIM)   // 264192

// Diagonal-major scratch: cell (t,u) at [d=t+u][col=u]. PITCH=136 floats
// (544B = 34 x 16B cp.async segments per row).
#define PITCH   136
#define DIAGS   (T_DIM + U_DIM)           // 384
#define DIAG_SZ (DIAGS * PITCH)           // 52224 per sample

#define NEG     (-1.0e30f)                // finite "-inf": exp underflows to 0
#define CH      4                         // diagonals per pipeline chunk
#define NCHUNK  96                        // 384 diagonals (d = 1..384)
#define SLOTS   16                        // smem ring rows = 4 chunks in flight

static __device__ __align__(16) float g_bld[N_DIM * DIAG_SZ + 512];  // blank
static __device__ __align__(16) float g_emd[N_DIM * DIAG_SZ + 512];  // emit
static __device__ float    g_loss[N_DIM];
static __device__ unsigned g_ticket;       // zero-init; last CTA resets to 0

__device__ __forceinline__ float laddexp(float x, float y) {
    float mx = fmaxf(x, y);
    return mx + __logf(1.0f + __expf(fminf(x, y) - mx));
}

__device__ __forceinline__ void cp16(unsigned int sdst, const void* gsrc) {
    asm volatile("cp.async.cg.shared.global [%0], [%1], 16;\n"
                 :: "r"(sdst), "l"(gsrc));
}
__device__ __forceinline__ void cp_commit() {
    asm volatile("cp.async.commit_group;\n" ::: "memory");
}
__device__ __forceinline__ void cp_wait3() {
    asm volatile("cp.async.wait_group 3;\n" ::: "memory");
}

// ---------------------------------------------------------------------------
// Kernel 0: flood scratch with NEG so unwritten pad slots act as -inf;
// edge cells in the wavefront then need no branches (dead path adds NEG,
// exp()==0, single-path result exactly).
// ---------------------------------------------------------------------------
__global__ void fill_kernel() {
    const int n4 = (N_DIM * DIAG_SZ + 512) / 4;
    float4 v = make_float4(NEG, NEG, NEG, NEG);
    float4* b = reinterpret_cast<float4*>(g_bld);
    float4* e = reinterpret_cast<float4*>(g_emd);
    for (int i = blockIdx.x * blockDim.x + threadIdx.x; i < n4;
         i += gridDim.x * blockDim.x) {
        b[i] = v;
        e[i] = v;
    }
}

// ---------------------------------------------------------------------------
// Kernel 1: per-row logsumexp over C=512; write blank/emit log-probs into
// diagonal-major scratch. One warp per row, 4x float4 per lane. HBM-bound
// (541 MB stream, measured at the DRAM ceiling).
// ---------------------------------------------------------------------------
__global__ void __launch_bounds__(256) lse_kernel(const float* __restrict__ act,
                                                  const int*   __restrict__ tgt) {
    int gw   = (blockIdx.x * 256 + threadIdx.x) >> 5;   // global warp = row id
    int lane = threadIdx.x & 31;
    if (gw >= ROWS) return;

    const float4* p4 = reinterpret_cast<const float4*>(act) + (size_t)gw * (C_DIM / 4);
    float4 a = p4[lane];
    float4 b = p4[lane + 32];
    float4 c = p4[lane + 64];
    float4 d = p4[lane + 96];

    float m = fmaxf(fmaxf(fmaxf(a.x, a.y), fmaxf(a.z, a.w)),
                    fmaxf(fmaxf(b.x, b.y), fmaxf(b.z, b.w)));
    m = fmaxf(m, fmaxf(fmaxf(fmaxf(c.x, c.y), fmaxf(c.z, c.w)),
                       fmaxf(fmaxf(d.x, d.y), fmaxf(d.z, d.w))));
#pragma unroll
    for (int o = 16; o; o >>= 1)
        m = fmaxf(m, __shfl_xor_sync(0xffffffffu, m, o));

    float s = __expf(a.x - m) + __expf(a.y - m) + __expf(a.z - m) + __expf(a.w - m);
    s += __expf(b.x - m) + __expf(b.y - m) + __expf(b.z - m) + __expf(b.w - m);
    s += __expf(c.x - m) + __expf(c.y - m) + __expf(c.z - m) + __expf(c.w - m);
    s += __expf(d.x - m) + __expf(d.y - m) + __expf(d.z - m) + __expf(d.w - m);
#pragma unroll
    for (int o = 16; o; o >>= 1)
        s += __shfl_xor_sync(0xffffffffu, s, o);

    if (lane == 0) {
        float lse = m + __logf(s);
        int n   = gw / (T_DIM * U1_DIM);
        int rem = gw % (T_DIM * U1_DIM);
        int t   = rem / U1_DIM;
        int u   = rem % U1_DIM;
        size_t db = (size_t)n * DIAG_SZ + (size_t)(t + u) * PITCH + u;
        g_bld[db] = a.x - lse;                 // lane 0's a.x == act[row, BLANK=0]
        if (u < U_DIM) {
            int tv = __ldg(tgt + n * U_DIM + u);
            g_emd[db] = __ldg(act + (size_t)gw * C_DIM + tv) - lse;  // L1-hot
        }
    }
}

// ---------------------------------------------------------------------------
// Kernel 2: alpha wavefront, ONE WARP per sample, register-resident state,
// cp.async smem pipeline for operands (16-row ring = 4 chunks in flight,
// fully hiding L2 latency; one wait_group+syncwarp per 4 diagonals).
//   cell (t,u), d=t+u:  alpha = laddexp(alpha[t-1][u] + bl@[d-1][u],
//                                       alpha[t][u-1] + em@[d-1][u-1])
// Lane L owns u = 4L+1..4L+4; u=0 is the blank-only FADD chain a0.
// Also folds the final mean: last CTA (ticket atomic) sums g_loss -> out.
// ---------------------------------------------------------------------------
__global__ void __launch_bounds__(32, 1) alpha_kernel(const int* __restrict__ tlen,
                                                      const int* __restrict__ ulen,
                                                      float* __restrict__ out) {
    __shared__ __align__(16) float s_bl[SLOTS][PITCH];
    __shared__ __align__(16) float s_em[SLOTS][PITCH];

    int n = blockIdx.x;
    int L = threadIdx.x;
    const float* bld = g_bld + (size_t)n * DIAG_SZ;
    const float* emd = g_emd + (size_t)n * DIAG_SZ;

    int Tn = __ldg(tlen + n);
    int Un = __ldg(ulen + n);
    int dLoss = Tn - 1 + Un;

    unsigned int sbl = (unsigned int)__cvta_generic_to_shared(&s_bl[0][0]);
    unsigned int sem = (unsigned int)__cvta_generic_to_shared(&s_em[0][0]);

    // Issue one row's copies (bl+em) into ring slot (row & 15).
    auto issue_row = [&](int row) {
        unsigned int so = (unsigned int)(row & (SLOTS - 1)) * (PITCH * 4);
        const float* gb = bld + (size_t)row * PITCH;
        const float* ge = emd + (size_t)row * PITCH;
        cp16(sbl + so + 16 * L, gb + 4 * L);
        cp16(sem + so + 16 * L, ge + 4 * L);
        if (L < 2) {                                   // segments 32,33
            cp16(sbl + so + 16 * (32 + L), gb + 4 * (32 + L));
            cp16(sem + so + 16 * (32 + L), ge + 4 * (32 + L));
        }
    };

    // Prologue: chunks 0..2 (rows 0..11), one commit group per chunk.
#pragma unroll
    for (int c = 0; c < 3; ++c) {
#pragma unroll
        for (int k = 0; k < CH; ++k) issue_row(4 * c + k);
        cp_commit();
    }

    float a0 = 0.0f;                          // alpha[0][0]
    float a[4] = {NEG, NEG, NEG, NEG};

    if (dLoss == 0 && L == 0)                 // degenerate Tn=1, Un=0
        g_loss[n] = -(a0 + __ldg(bld));

    int d = 1;
    for (int c = 0; c < NCHUNK; ++c) {
        int rf = 4 * (c + 3);                 // first row of chunk c+3
        if (rf < DIAGS) {
#pragma unroll
            for (int k = 0; k < CH; ++k) issue_row(rf + k);
        }
        cp_commit();                          // commit (possibly empty) group
        cp_wait3();                           // chunk c's rows are resident
        __syncwarp();

#pragma unroll
        for (int k = 0; k < CH; ++k, ++d) {
            int s = (d - 1) & (SLOTS - 1);
            float4 bl4 = *reinterpret_cast<const float4*>(&s_bl[s][4 * L]);
            float4 em4 = *reinterpret_cast<const float4*>(&s_em[s][4 * L]);
            float  blx = s_bl[s][4 * L + 4];
            float  bl00 = s_bl[s][0];         // uniform broadcast LDS

            float nb_in = __shfl_up_sync(0xffffffffu, a[3], 1);  // aprev[4L]
            float nb    = (L == 0) ? a0 : nb_in;

            // cells u = 4L+1..4L+4 (bl col u -> bl4.yzw/blx; em col u-1 -> em4)
            float t0 = laddexp(a[0] + bl4.y, nb   + em4.x);
            float t1 = laddexp(a[1] + bl4.z, a[0] + em4.y);
            float t2 = laddexp(a[2] + bl4.w, a[1] + em4.z);
            float t3 = laddexp(a[3] + blx,   a[2] + em4.w);
            a0 += bl00;                        // u=0 blank-only chain
            a[0] = t0; a[1] = t1; a[2] = t2; a[3] = t3;

            if (d == dLoss) {                  // warp-uniform, true once
                float fin = __ldg(bld + (size_t)dLoss * PITCH + Un);
                if (Un == 0) {
                    if (L == 0) g_loss[n] = -(a0 + fin);
                } else {
                    int tl = (Un - 1) >> 2, j = (Un - 1) & 3;
                    float v = (j == 0) ? t0 : (j == 1) ? t1 : (j == 2) ? t2 : t3;
                    float lv = __shfl_sync(0xffffffffu, v, tl);
                    if (L == 0) g_loss[n] = -(lv + fin);
                }
            }
        }
    }

    // Fold the mean: last CTA to arrive sums all losses in fixed order.
    __syncwarp();
    __threadfence();
    if (L == 0) {
        unsigned t = atomicAdd(&g_ticket, 1u);
        if (t == N_DIM - 1) {
            __threadfence();
            float s = 0.0f;
#pragma unroll
            for (int i = 0; i < N_DIM; ++i) s += g_loss[i];
            out[0] = s / (float)N_DIM;
            g_ticket = 0;                      // reset for next graph replay
        }
    }
}

extern "C" void kernel_launch(void* const* d_in, const int* in_sizes, int n_in,
                              void* d_out, int out_size) {
    const float* act  = (const float*)d_in[0];
    const int*   tgt  = (const int*)  d_in[1];
    const int*   tlen = (const int*)  d_in[2];
    const int*   ulen = (const int*)  d_in[3];
    float*       out  = (float*)      d_out;

    fill_kernel<<<400, 256>>>();
    int blocks = (ROWS + 7) / 8;              // one warp per row, 8 warps/block
    lse_kernel<<<blocks, 256>>>(act, tgt);
    alpha_kernel<<<N_DIM, 32>>>(tlen, ulen, out);
}